// round 15
// baseline (speedup 1.0000x reference)
#include <cuda_runtime.h>
#include <cuda_fp16.h>
#include <math.h>
#include <stdint.h>

// Problem constants (fixed shapes)
#define BV      4
#define SEQ     4096
#define DIM     1024
#define WIN     512
#define HEADS   16
#define DH      64
#define MROWS   (BV * SEQ)     // 16384
#define N3      (3 * DIM)      // 3072
#define NEG_INF_F (-1e9f)

// ---------------------------------------------------------------------------
// Scratch (device globals: sanctioned workaround for the no-alloc rule)
// ---------------------------------------------------------------------------
__device__ __half g_xh[(size_t)MROWS * DIM];
__device__ __half g_wqkvt[(size_t)N3 * DIM];     // W_qkv^T [N3, K] fp16
__device__ __half g_wot[(size_t)DIM * DIM];      // W_o^T  [N, K] fp16
__device__ __half g_qkvh[(size_t)MROWS * N3];    // 96 MB
__device__ __half g_ah[(size_t)MROWS * DIM];

// ---------------------------------------------------------------------------
// Helpers (sm_80-portable ISA: mma.sync + cp.async + ldmatrix)
// ---------------------------------------------------------------------------
__device__ __forceinline__ uint32_t smem_u32(const void* p) {
    uint32_t a;
    asm("{ .reg .u64 t; cvta.to.shared.u64 t, %1; cvt.u32.u64 %0, t; }"
        : "=r"(a) : "l"(p));
    return a;
}
#define CP16(dst, src) \
    asm volatile("cp.async.cg.shared.global [%0], [%1], 16;" \
                 :: "r"(dst), "l"(src) : "memory")
#define CP_COMMIT() asm volatile("cp.async.commit_group;" ::: "memory")
#define CP_WAIT1()  asm volatile("cp.async.wait_group 1;" ::: "memory")
#define CP_WAIT0()  asm volatile("cp.async.wait_group 0;" ::: "memory")

#define LDSM_X4(r0, r1, r2, r3, a) \
    asm volatile("ldmatrix.sync.aligned.m8n8.x4.shared.b16 {%0,%1,%2,%3}, [%4];" \
                 : "=r"(r0), "=r"(r1), "=r"(r2), "=r"(r3) : "r"(a))
#define LDSM_X4T(r0, r1, r2, r3, a) \
    asm volatile("ldmatrix.sync.aligned.m8n8.x4.trans.shared.b16 {%0,%1,%2,%3}, [%4];" \
                 : "=r"(r0), "=r"(r1), "=r"(r2), "=r"(r3) : "r"(a))

__device__ __forceinline__ void mma16816(float* d, const uint32_t* a, const uint32_t* b) {
    asm volatile(
        "mma.sync.aligned.m16n8k16.row.col.f32.f16.f16.f32 "
        "{%0,%1,%2,%3}, {%4,%5,%6,%7}, {%8,%9}, {%0,%1,%2,%3};"
        : "+f"(d[0]), "+f"(d[1]), "+f"(d[2]), "+f"(d[3])
        : "r"(a[0]), "r"(a[1]), "r"(a[2]), "r"(a[3]), "r"(b[0]), "r"(b[1]));
}

__device__ __forceinline__ uint32_t packh2(float a, float b) {
    __half2 t = __floats2half2_rn(a, b);
    return *reinterpret_cast<uint32_t*>(&t);
}

// ---------------------------------------------------------------------------
// fp16 HMMA GEMM: C[M,N] = A[M,K] @ B^T + bias  (A, B fp16; B stored [N,K])
// R6's proven high-occupancy shape, 1-product math:
// CTA 128x128, 512 threads (16 warps, 32x32 warp tiles), BK=16/stage,
// 3-stage cp.async pipeline (24KB), prefetch-after-barrier, 6 LDSM -> 8 MMAs
// per warp per chunk. Target: regs <= 64 -> 2 CTAs/SM -> 32 warps/SM
// (the occupancy that made R6 hit tensor=68%).
// OUTH=1: fp16 C + bias.  OUTH=0: fp32 C + bias.
// Smem rows 32B (2 x 16B chunks), phys chunk = chunk ^ ((row>>2)&1).
// ---------------------------------------------------------------------------
template<int OUTH>
__global__ __launch_bounds__(512, 2) void gemm_hmma(
    const __half* __restrict__ A, const __half* __restrict__ Bh,
    const float* __restrict__ bias, float* __restrict__ C,
    __half* __restrict__ Ch,
    int M, int N, int K)
{
    __shared__ char sm[24576];          // 3 stages x (A 4KB + B 4KB)
    const uint32_t sb = smem_u32(sm);

    const int tid  = threadIdx.x;
    const int lane = tid & 31, wid = tid >> 5;
    const int g = lane >> 2, tig = lane & 3;
    const int jj = lane & 7, grp = lane >> 3;
    const int wm = (wid >> 2) * 32;     // 4 warp rows
    const int wn = (wid & 3) * 32;      // 4 warp cols
    const int row0 = blockIdx.y * 128, col0 = blockIdx.x * 128;

    // cp.async mapping: tid<256 -> A chunk, tid>=256 -> B chunk (1 CP16/stage)
    const int lr = (tid & 255) >> 1;    // row 0..127
    const int lc = tid & 1;             // 16B chunk 0/1
    const uint32_t swoff = (tid < 256 ? 0 : 4096) +
                           lr * 32 + ((lc ^ ((lr >> 2) & 1)) << 4);
    const __half* gsrc0 = (tid < 256)
        ? A  + (size_t)(row0 + lr) * K + lc * 8
        : Bh + (size_t)(col0 + lr) * K + lc * 8;

    // ldmatrix per-lane relative offsets (stage-invariant)
    uint32_t aoff[2], boff[2];
#pragma unroll
    for (int mt = 0; mt < 2; mt++) {
        int r = wm + mt * 16 + (grp & 1) * 8 + jj;
        int c = grp >> 1;
        aoff[mt] = r * 32 + ((c ^ ((r >> 2) & 1)) << 4);
    }
#pragma unroll
    for (int pr = 0; pr < 2; pr++) {
        int r = wn + pr * 16 + (grp >> 1) * 8 + jj;
        int c = grp & 1;
        boff[pr] = 4096 + r * 32 + ((c ^ ((r >> 2) & 1)) << 4);
    }

    float acc[2][4][4];
#pragma unroll
    for (int mt = 0; mt < 2; mt++)
#pragma unroll
        for (int nf = 0; nf < 4; nf++)
#pragma unroll
            for (int j = 0; j < 4; j++) acc[mt][nf][j] = 0.f;

    const int nch = K >> 4;             // 64 chunks for K=1024

    // Prologue: stages 0 and 1
    CP16(sb + swoff, gsrc0);
    CP_COMMIT();
    CP16(sb + 8192 + swoff, gsrc0 + 16);
    CP_COMMIT();

    uint32_t cur = 0, pre = 16384;      // byte offsets of stage kc and kc+2
    for (int kc = 0; kc < nch; kc++) {
        if (kc + 1 < nch) { CP_WAIT1(); } else { CP_WAIT0(); }
        __syncthreads();
        if (kc + 2 < nch) {
            CP16(sb + pre + swoff, gsrc0 + (kc + 2) * 16);
            CP_COMMIT();
        }

        const uint32_t st = sb + cur;
        uint32_t ah[2][4], bh[4][2];
        LDSM_X4(ah[0][0], ah[0][1], ah[0][2], ah[0][3], st + aoff[0]);
        LDSM_X4(ah[1][0], ah[1][1], ah[1][2], ah[1][3], st + aoff[1]);
        LDSM_X4(bh[0][0], bh[0][1], bh[1][0], bh[1][1], st + boff[0]);
        LDSM_X4(bh[2][0], bh[2][1], bh[3][0], bh[3][1], st + boff[1]);

#pragma unroll
        for (int mt = 0; mt < 2; mt++)
#pragma unroll
            for (int nf = 0; nf < 4; nf++)
                mma16816(acc[mt][nf], ah[mt], bh[nf]);

        cur = (cur == 16384) ? 0 : cur + 8192;
        pre = (pre == 16384) ? 0 : pre + 8192;
    }

#pragma unroll
    for (int mt = 0; mt < 2; mt++) {
        const int r = row0 + wm + mt * 16 + g;
#pragma unroll
        for (int nf = 0; nf < 4; nf++) {
            const int c = col0 + wn + nf * 8 + tig * 2;
            const float bx = bias[c], by = bias[c + 1];
            float v00 = acc[mt][nf][0] + bx, v01 = acc[mt][nf][1] + by;
            float v10 = acc[mt][nf][2] + bx, v11 = acc[mt][nf][3] + by;
            if (OUTH) {
                *(__half2*)&Ch[(size_t)r * N + c]       = __floats2half2_rn(v00, v01);
                *(__half2*)&Ch[(size_t)(r + 8) * N + c] = __floats2half2_rn(v10, v11);
            } else {
                float2 a0 = { v00, v01 }, a1 = { v10, v11 };
                *(float2*)&C[(size_t)r * N + c]       = a0;
                *(float2*)&C[(size_t)(r + 8) * N + c] = a1;
            }
        }
    }
}

// ---------------------------------------------------------------------------
// fp32 -> fp16 convert (elementwise)
// ---------------------------------------------------------------------------
__global__ __launch_bounds__(256) void cvt_kernel(
    const float4* __restrict__ in, __half* __restrict__ hi, int n4)
{
    int i = blockIdx.x * 256 + threadIdx.x;
    if (i >= n4) return;
    float4 v = in[i];
    ((__half2*)hi)[2 * i + 0] = __floats2half2_rn(v.x, v.y);
    ((__half2*)hi)[2 * i + 1] = __floats2half2_rn(v.z, v.w);
}

// ---------------------------------------------------------------------------
// Transpose: W [K, N] fp32 -> Wt [N, K] fp16 (weights)
// ---------------------------------------------------------------------------
__global__ __launch_bounds__(256) void tsplit_kernel(
    const float* __restrict__ W, __half* __restrict__ Th, int K, int N)
{
    __shared__ float t[32][33];
    const int nb = blockIdx.x * 32, kb = blockIdx.y * 32;
    const int tx = threadIdx.x, ty = threadIdx.y;
    for (int y = ty; y < 32; y += 8)
        t[y][tx] = W[(size_t)(kb + y) * N + nb + tx];
    __syncthreads();
    for (int y = ty; y < 32; y += 8)
        Th[(size_t)(nb + y) * K + kb + tx] = __float2half(t[tx][y]);
}

// ---------------------------------------------------------------------------
// Windowed causal attention, plain-fp16 HMMA flash kernel, KV-TILE 64
// (unchanged from R13 — measured best).
// Block: 128 threads (4 warps). Grid: (8 q-tiles of 64 rows, 32 win x 16 heads).
// Smem (40KB): Q 8K | stage{0,1}: K 8K, V 8K.
// ---------------------------------------------------------------------------
__device__ __forceinline__ void attn_load_kv(
    uint32_t sstage, const __half* q_g, size_t rowbase, int tid)
{
#pragma unroll
    for (int it = 0; it < 8; it++) {
        int i = tid + it * 128;                 // 0..1023
        int buf = i >> 9, within = i & 511;     // buf 0=K, 1=V (64 rows each)
        int r = within >> 3, c = within & 7;
        uint32_t dst = sstage + buf * 8192 + r * 128 + ((c ^ (r & 7)) << 4);
        size_t go = rowbase + (size_t)r * N3 + c * 8 + (buf ? 2 * DIM : DIM);
        CP16(dst, q_g + go);
    }
}

__global__ __launch_bounds__(128) void attn_hmma(
    const __half* __restrict__ q_g, __half* __restrict__ oh)
{
    const int qt  = blockIdx.x;          // 0..7
    const int wh  = blockIdx.y;          // 0..511
    const int win = wh >> 4, h = wh & 15;
    const int mbase = win * WIN;
    const int qcol  = h * DH;
    const int tid = threadIdx.x, lane = tid & 31, w = tid >> 5;
    const int g = lane >> 2, tig = lane & 3;
    const int jj = lane & 7, grp = lane >> 3;

    __shared__ char sm[40960];           // Q 8K + 2 x (K 8K + V 8K)
    const uint32_t sb = smem_u32(sm);

    for (int i = tid; i < 512; i += 128) {
        int r = i >> 3, c = i & 7;
        uint32_t off = r * 128 + ((c ^ (r & 7)) << 4);
        size_t gsrc = (size_t)(mbase + qt * 64 + r) * N3 + qcol + c * 8;
        *(uint4*)(sm + off) = *(const uint4*)(q_g + gsrc);
    }

    const int ktmax = qt;                // KV tiles of 64 rows
    attn_load_kv(sb + 8192, q_g, (size_t)mbase * N3 + qcol, tid);
    CP_COMMIT();
    __syncthreads();

    uint32_t qf[4][4];
    const int qrow = w * 16 + (grp & 1) * 8 + jj;
#pragma unroll
    for (int kk = 0; kk < 4; kk++) {
        int c = 2 * kk + (grp >> 1);
        uint32_t off = qrow * 128 + ((c ^ (qrow & 7)) << 4);
        LDSM_X4(qf[kk][0], qf[kk][1], qf[kk][2], qf[kk][3], sb + off);
    }

    float m0 = -INFINITY, m1 = -INFINITY, l0 = 0.f, l1 = 0.f;
    float oacc[8][4];
#pragma unroll
    for (int nt = 0; nt < 8; nt++)
#pragma unroll
        for (int j = 0; j < 4; j++) oacc[nt][j] = 0.f;

    const int gq0 = qt * 64 + w * 16 + g;
    const int gq1 = gq0 + 8;
    const int krowb = (grp >> 1) * 8 + jj;
    const int vrow0 = (grp & 1) * 8 + jj;

    for (int kt = 0; kt <= ktmax; kt++) {
        CP_WAIT0();
        __syncthreads();
        if (kt < ktmax) {
            attn_load_kv(sb + 8192 + ((kt + 1) & 1) * 16384, q_g,
                         (size_t)(mbase + (kt + 1) * 64) * N3 + qcol, tid);
            CP_COMMIT();
        }

        const uint32_t stg = sb + 8192 + (kt & 1) * 16384;

        float sacc[8][4];
#pragma unroll
        for (int nt = 0; nt < 8; nt++)
#pragma unroll
            for (int j = 0; j < 4; j++) sacc[nt][j] = 0.f;

#pragma unroll
        for (int kk = 0; kk < 4; kk++) {
            uint32_t kb[8][2];
#pragma unroll
            for (int pr = 0; pr < 4; pr++) {
                int r = pr * 16 + krowb;
                int c = 2 * kk + (grp & 1);
                uint32_t off = r * 128 + ((c ^ (r & 7)) << 4);
                LDSM_X4(kb[pr*2][0], kb[pr*2][1], kb[pr*2+1][0], kb[pr*2+1][1],
                        stg + off);
            }
#pragma unroll
            for (int nt = 0; nt < 8; nt++)
                mma16816(sacc[nt], qf[kk], kb[nt]);
        }

#pragma unroll
        for (int nt = 0; nt < 8; nt++) {
            int colb = kt * 64 + nt * 8 + 2 * tig;
            sacc[nt][0] = (colb     > gq0) ? NEG_INF_F : sacc[nt][0] * 0.125f;
            sacc[nt][1] = (colb + 1 > gq0) ? NEG_INF_F : sacc[nt][1] * 0.125f;
            sacc[nt][2] = (colb     > gq1) ? NEG_INF_F : sacc[nt][2] * 0.125f;
            sacc[nt][3] = (colb + 1 > gq1) ? NEG_INF_F : sacc[nt][3] * 0.125f;
        }

        float rm0 = -INFINITY, rm1 = -INFINITY;
#pragma unroll
        for (int nt = 0; nt < 8; nt++) {
            rm0 = fmaxf(rm0, fmaxf(sacc[nt][0], sacc[nt][1]));
            rm1 = fmaxf(rm1, fmaxf(sacc[nt][2], sacc[nt][3]));
        }
        rm0 = fmaxf(rm0, __shfl_xor_sync(0xffffffffu, rm0, 1));
        rm0 = fmaxf(rm0, __shfl_xor_sync(0xffffffffu, rm0, 2));
        rm1 = fmaxf(rm1, __shfl_xor_sync(0xffffffffu, rm1, 1));
        rm1 = fmaxf(rm1, __shfl_xor_sync(0xffffffffu, rm1, 2));

        float mn0 = fmaxf(m0, rm0), mn1 = fmaxf(m1, rm1);
        float corr0 = __expf(m0 - mn0), corr1 = __expf(m1 - mn1);
        m0 = mn0; m1 = mn1;

        float rs0 = 0.f, rs1 = 0.f;
#pragma unroll
        for (int nt = 0; nt < 8; nt++) {
            sacc[nt][0] = __expf(sacc[nt][0] - mn0);
            sacc[nt][1] = __expf(sacc[nt][1] - mn0);
            sacc[nt][2] = __expf(sacc[nt][2] - mn1);
            sacc[nt][3] = __expf(sacc[nt][3] - mn1);
            rs0 += sacc[nt][0] + sacc[nt][1];
            rs1 += sacc[nt][2] + sacc[nt][3];
        }
        rs0 += __shfl_xor_sync(0xffffffffu, rs0, 1);
        rs0 += __shfl_xor_sync(0xffffffffu, rs0, 2);
        rs1 += __shfl_xor_sync(0xffffffffu, rs1, 1);
        rs1 += __shfl_xor_sync(0xffffffffu, rs1, 2);
        l0 = l0 * corr0 + rs0;
        l1 = l1 * corr1 + rs1;

#pragma unroll
        for (int nt = 0; nt < 8; nt++) {
            oacc[nt][0] *= corr0; oacc[nt][1] *= corr0;
            oacc[nt][2] *= corr1; oacc[nt][3] *= corr1;
        }

        uint32_t pa[4][4];
#pragma unroll
        for (int kk2 = 0; kk2 < 4; kk2++) {
            int a = 2 * kk2, b = a + 1;
            pa[kk2][0] = packh2(sacc[a][0], sacc[a][1]);
            pa[kk2][1] = packh2(sacc[a][2], sacc[a][3]);
            pa[kk2][2] = packh2(sacc[b][0], sacc[b][1]);
            pa[kk2][3] = packh2(sacc[b][2], sacc[b][3]);
        }

#pragma unroll
        for (int kk2 = 0; kk2 < 4; kk2++) {
            int r = kk2 * 16 + vrow0;
#pragma unroll
            for (int pr = 0; pr < 4; pr++) {
                int c = pr * 2 + (grp >> 1);
                uint32_t off = r * 128 + ((c ^ (r & 7)) << 4);
                uint32_t v0[2], v1[2];
                LDSM_X4T(v0[0], v0[1], v1[0], v1[1], stg + 8192 + off);
                mma16816(oacc[pr*2],   pa[kk2], v0);
                mma16816(oacc[pr*2+1], pa[kk2], v1);
            }
        }
    }

    const float inv0 = 1.f / l0, inv1 = 1.f / l1;
    const size_t r0 = (size_t)(mbase + qt * 64 + w * 16 + g);
    const size_t r1 = r0 + 8;
#pragma unroll
    for (int nt = 0; nt < 8; nt++) {
        int c = qcol + nt * 8 + tig * 2;
        *(__half2*)&oh[r0 * DIM + c] =
            __floats2half2_rn(oacc[nt][0] * inv0, oacc[nt][1] * inv0);
        *(__half2*)&oh[r1 * DIM + c] =
            __floats2half2_rn(oacc[nt][2] * inv1, oacc[nt][3] * inv1);
    }
}

// ---------------------------------------------------------------------------
extern "C" void kernel_launch(void* const* d_in, const int* in_sizes, int n_in,
                              void* d_out, int out_size)
{
    (void)in_sizes; (void)n_in; (void)out_size;
    const float* x     = (const float*)d_in[0];
    const float* w_qkv = (const float*)d_in[1];
    const float* b_qkv = (const float*)d_in[2];
    const float* w_o   = (const float*)d_in[3];
    const float* b_o   = (const float*)d_in[4];
    float* out = (float*)d_out;

    __half *xh, *wqt, *wot, *qkvh, *ah;
    cudaGetSymbolAddress((void**)&xh,   g_xh);
    cudaGetSymbolAddress((void**)&wqt,  g_wqkvt);
    cudaGetSymbolAddress((void**)&wot,  g_wot);
    cudaGetSymbolAddress((void**)&qkvh, g_qkvh);
    cudaGetSymbolAddress((void**)&ah,   g_ah);

    // 1) Convert x to fp16
    {
        int n4 = MROWS * DIM / 4;
        cvt_kernel<<<n4 / 256, 256>>>((const float4*)x, xh, n4);
    }
    // 2) Transpose weights to fp16
    tsplit_kernel<<<dim3(N3 / 32, DIM / 32), dim3(32, 8)>>>(w_qkv, wqt, DIM, N3);
    tsplit_kernel<<<dim3(DIM / 32, DIM / 32), dim3(32, 8)>>>(w_o, wot, DIM, DIM);

    // 3) QKV projection -> fp16 output (512 threads, 32 warps/SM target)
    gemm_hmma<1><<<dim3(N3 / 128, MROWS / 128), 512>>>(
        xh, wqt, b_qkv, nullptr, qkvh, MROWS, N3, DIM);

    // 4) Windowed causal attention (plain fp16 HMMA flash, KV-tile 64) -> fp16
    attn_hmma<<<dim3(8, 512), 128>>>(qkvh, ah);

    // 5) Output projection -> fp32 final output
    gemm_hmma<0><<<dim3(DIM / 128, MROWS / 128), 512>>>(
        ah, wot, b_o, out, nullptr, MROWS, DIM, DIM);
}

// round 17
// speedup vs baseline: 1.1593x; 1.1593x over previous
#include <cuda_runtime.h>
#include <cuda_fp16.h>
#include <math.h>
#include <stdint.h>

// Problem constants (fixed shapes)
#define BV      4
#define SEQ     4096
#define DIM     1024
#define WIN     512
#define HEADS   16
#define DH      64
#define MROWS   (BV * SEQ)     // 16384
#define N3      (3 * DIM)      // 3072
#define NEG_INF_F (-1e9f)

// ---------------------------------------------------------------------------
// Scratch (device globals: sanctioned workaround for the no-alloc rule)
// ---------------------------------------------------------------------------
__device__ __half g_xh[(size_t)MROWS * DIM];
__device__ __half g_wqkvt[(size_t)N3 * DIM];     // W_qkv^T [N3, K] fp16
__device__ __half g_wot[(size_t)DIM * DIM];      // W_o^T  [N, K] fp16
__device__ __half g_qkvh[(size_t)MROWS * N3];    // 96 MB
__device__ __half g_ah[(size_t)MROWS * DIM];

// ---------------------------------------------------------------------------
// Helpers (sm_80-portable ISA: mma.sync + cp.async + ldmatrix)
// ---------------------------------------------------------------------------
__device__ __forceinline__ uint32_t smem_u32(const void* p) {
    uint32_t a;
    asm("{ .reg .u64 t; cvta.to.shared.u64 t, %1; cvt.u32.u64 %0, t; }"
        : "=r"(a) : "l"(p));
    return a;
}
#define CP16(dst, src) \
    asm volatile("cp.async.cg.shared.global [%0], [%1], 16;" \
                 :: "r"(dst), "l"(src) : "memory")
#define CP_COMMIT() asm volatile("cp.async.commit_group;" ::: "memory")
#define CP_WAIT1()  asm volatile("cp.async.wait_group 1;" ::: "memory")
#define CP_WAIT0()  asm volatile("cp.async.wait_group 0;" ::: "memory")

#define LDSM_X4(r0, r1, r2, r3, a) \
    asm volatile("ldmatrix.sync.aligned.m8n8.x4.shared.b16 {%0,%1,%2,%3}, [%4];" \
                 : "=r"(r0), "=r"(r1), "=r"(r2), "=r"(r3) : "r"(a))
#define LDSM_X4T(r0, r1, r2, r3, a) \
    asm volatile("ldmatrix.sync.aligned.m8n8.x4.trans.shared.b16 {%0,%1,%2,%3}, [%4];" \
                 : "=r"(r0), "=r"(r1), "=r"(r2), "=r"(r3) : "r"(a))

__device__ __forceinline__ void mma16816(float* d, const uint32_t* a, const uint32_t* b) {
    asm volatile(
        "mma.sync.aligned.m16n8k16.row.col.f32.f16.f16.f32 "
        "{%0,%1,%2,%3}, {%4,%5,%6,%7}, {%8,%9}, {%0,%1,%2,%3};"
        : "+f"(d[0]), "+f"(d[1]), "+f"(d[2]), "+f"(d[3])
        : "r"(a[0]), "r"(a[1]), "r"(a[2]), "r"(a[3]), "r"(b[0]), "r"(b[1]));
}

__device__ __forceinline__ uint32_t packh2(float a, float b) {
    __half2 t = __floats2half2_rn(a, b);
    return *reinterpret_cast<uint32_t*>(&t);
}

// ---------------------------------------------------------------------------
// fp16 HMMA GEMM (R11/R13 measured-best body — CONVERGED, do not touch):
// C[M,N] = A[M,K] @ B^T + bias  (A, B fp16; B stored [N,K])
// CTA 128x128, 256 threads (8 warps, 32x64 warp tiles), BK=16/stage,
// 3-stage cp.async pipeline (24KB), prefetch-after-barrier, in-iteration
// ldmatrix -> 16 MMAs, static stage addressing.
// OUTH=1: fp16 C + bias.  OUTH=0: fp32 C + bias.
// Smem rows 32B (2 x 16B chunks), phys chunk = chunk ^ ((row>>2)&1).
// ---------------------------------------------------------------------------
template<int OUTH>
__global__ __launch_bounds__(256, 2) void gemm_hmma(
    const __half* __restrict__ A, const __half* __restrict__ Bh,
    const float* __restrict__ bias, float* __restrict__ C,
    __half* __restrict__ Ch,
    int M, int N, int K)
{
    __shared__ char sm[24576];          // 3 stages x (A 4KB + B 4KB)
    const uint32_t sb = smem_u32(sm);

    const int tid  = threadIdx.x;
    const int lane = tid & 31, wid = tid >> 5;
    const int g = lane >> 2, tig = lane & 3;
    const int jj = lane & 7, grp = lane >> 3;
    const int wm = (wid & 3) * 32;      // 4 warps down M
    const int wn = (wid >> 2) * 64;     // 2 warps across N
    const int row0 = blockIdx.y * 128, col0 = blockIdx.x * 128;

    const int lr = tid >> 1;
    const int lc = tid & 1;
    const uint32_t swoff = lr * 32 + ((lc ^ ((lr >> 2) & 1)) << 4);
    const __half* gA0 = A  + (size_t)(row0 + lr) * K + lc * 8;
    const __half* gB0 = Bh + (size_t)(col0 + lr) * K + lc * 8;

    uint32_t aoff[2], boff[4];
#pragma unroll
    for (int mt = 0; mt < 2; mt++) {
        int r = wm + mt * 16 + (grp & 1) * 8 + jj;
        int c = grp >> 1;
        aoff[mt] = r * 32 + ((c ^ ((r >> 2) & 1)) << 4);
    }
#pragma unroll
    for (int bt = 0; bt < 4; bt++) {
        int r = wn + bt * 16 + (grp >> 1) * 8 + jj;
        int c = grp & 1;
        boff[bt] = r * 32 + ((c ^ ((r >> 2) & 1)) << 4);
    }

    float acc[2][8][4];
#pragma unroll
    for (int mt = 0; mt < 2; mt++)
#pragma unroll
        for (int nf = 0; nf < 8; nf++)
#pragma unroll
            for (int j = 0; j < 4; j++) acc[mt][nf][j] = 0.f;

    const int nch = K >> 4;

    CP16(sb + swoff, gA0);               CP16(sb + 4096 + swoff, gB0);
    CP_COMMIT();
    CP16(sb + 8192 + swoff, gA0 + 16);   CP16(sb + 12288 + swoff, gB0 + 16);
    CP_COMMIT();

    uint32_t cur = 0, pre = 16384;
    for (int kc = 0; kc < nch; kc++) {
        if (kc + 1 < nch) { CP_WAIT1(); } else { CP_WAIT0(); }
        __syncthreads();
        if (kc + 2 < nch) {
            const int ko = (kc + 2) * 16;
            CP16(sb + pre + swoff, gA0 + ko);
            CP16(sb + pre + 4096 + swoff, gB0 + ko);
            CP_COMMIT();
        }

        const uint32_t st = sb + cur;
        uint32_t ah[2][4], bh[8][2];
        LDSM_X4(ah[0][0], ah[0][1], ah[0][2], ah[0][3], st + aoff[0]);
        LDSM_X4(ah[1][0], ah[1][1], ah[1][2], ah[1][3], st + aoff[1]);
#pragma unroll
        for (int bt = 0; bt < 4; bt++)
            LDSM_X4(bh[2*bt][0], bh[2*bt][1], bh[2*bt+1][0], bh[2*bt+1][1],
                    st + 4096 + boff[bt]);

#pragma unroll
        for (int mt = 0; mt < 2; mt++)
#pragma unroll
            for (int nf = 0; nf < 8; nf++)
                mma16816(acc[mt][nf], ah[mt], bh[nf]);

        cur = (cur == 16384) ? 0 : cur + 8192;
        pre = (pre == 16384) ? 0 : pre + 8192;
    }

#pragma unroll
    for (int mt = 0; mt < 2; mt++) {
        const int r = row0 + wm + mt * 16 + g;
#pragma unroll
        for (int nf = 0; nf < 8; nf++) {
            const int c = col0 + wn + nf * 8 + tig * 2;
            const float bx = bias[c], by = bias[c + 1];
            float v00 = acc[mt][nf][0] + bx, v01 = acc[mt][nf][1] + by;
            float v10 = acc[mt][nf][2] + bx, v11 = acc[mt][nf][3] + by;
            if (OUTH) {
                *(__half2*)&Ch[(size_t)r * N + c]       = __floats2half2_rn(v00, v01);
                *(__half2*)&Ch[(size_t)(r + 8) * N + c] = __floats2half2_rn(v10, v11);
            } else {
                float2 a0 = { v00, v01 }, a1 = { v10, v11 };
                *(float2*)&C[(size_t)r * N + c]       = a0;
                *(float2*)&C[(size_t)(r + 8) * N + c] = a1;
            }
        }
    }
}

// ---------------------------------------------------------------------------
// fp32 -> fp16 convert (elementwise)
// ---------------------------------------------------------------------------
__global__ __launch_bounds__(256) void cvt_kernel(
    const float4* __restrict__ in, __half* __restrict__ hi, int n4)
{
    int i = blockIdx.x * 256 + threadIdx.x;
    if (i >= n4) return;
    float4 v = in[i];
    ((__half2*)hi)[2 * i + 0] = __floats2half2_rn(v.x, v.y);
    ((__half2*)hi)[2 * i + 1] = __floats2half2_rn(v.z, v.w);
}

// ---------------------------------------------------------------------------
// Transpose: W [K, N] fp32 -> Wt [N, K] fp16 (weights)
// ---------------------------------------------------------------------------
__global__ __launch_bounds__(256) void tsplit_kernel(
    const float* __restrict__ W, __half* __restrict__ Th, int K, int N)
{
    __shared__ float t[32][33];
    const int nb = blockIdx.x * 32, kb = blockIdx.y * 32;
    const int tx = threadIdx.x, ty = threadIdx.y;
    for (int y = ty; y < 32; y += 8)
        t[y][tx] = W[(size_t)(kb + y) * N + nb + tx];
    __syncthreads();
    for (int y = ty; y < 32; y += 8)
        Th[(size_t)(nb + y) * K + kb + tx] = __float2half(t[tx][y]);
}

// ---------------------------------------------------------------------------
// Windowed causal attention, plain-fp16 HMMA flash kernel, KV-TILE 64
// (R13 measured-best body). LONGEST-FIRST scheduling: qt = 7 - blockIdx.x
// so the CTAs with the most KV tiles launch first (kills the tail skew).
// Block: 128 threads (4 warps). Grid: (8 q-tiles of 64 rows, 32 win x 16 heads).
// Smem (40KB): Q 8K | stage{0,1}: K 8K, V 8K.
// ---------------------------------------------------------------------------
__device__ __forceinline__ void attn_load_kv(
    uint32_t sstage, const __half* q_g, size_t rowbase, int tid)
{
#pragma unroll
    for (int it = 0; it < 8; it++) {
        int i = tid + it * 128;                 // 0..1023
        int buf = i >> 9, within = i & 511;     // buf 0=K, 1=V (64 rows each)
        int r = within >> 3, c = within & 7;
        uint32_t dst = sstage + buf * 8192 + r * 128 + ((c ^ (r & 7)) << 4);
        size_t go = rowbase + (size_t)r * N3 + c * 8 + (buf ? 2 * DIM : DIM);
        CP16(dst, q_g + go);
    }
}

__global__ __launch_bounds__(128) void attn_hmma(
    const __half* __restrict__ q_g, __half* __restrict__ oh)
{
    const int qt  = 7 - blockIdx.x;      // longest-first (qt=7 has 8 KV tiles)
    const int wh  = blockIdx.y;          // 0..511
    const int win = wh >> 4, h = wh & 15;
    const int mbase = win * WIN;
    const int qcol  = h * DH;
    const int tid = threadIdx.x, lane = tid & 31, w = tid >> 5;
    const int g = lane >> 2, tig = lane & 3;
    const int jj = lane & 7, grp = lane >> 3;

    __shared__ char sm[40960];           // Q 8K + 2 x (K 8K + V 8K)
    const uint32_t sb = smem_u32(sm);

    for (int i = tid; i < 512; i += 128) {
        int r = i >> 3, c = i & 7;
        uint32_t off = r * 128 + ((c ^ (r & 7)) << 4);
        size_t gsrc = (size_t)(mbase + qt * 64 + r) * N3 + qcol + c * 8;
        *(uint4*)(sm + off) = *(const uint4*)(q_g + gsrc);
    }

    const int ktmax = qt;                // KV tiles of 64 rows
    attn_load_kv(sb + 8192, q_g, (size_t)mbase * N3 + qcol, tid);
    CP_COMMIT();
    __syncthreads();

    uint32_t qf[4][4];
    const int qrow = w * 16 + (grp & 1) * 8 + jj;
#pragma unroll
    for (int kk = 0; kk < 4; kk++) {
        int c = 2 * kk + (grp >> 1);
        uint32_t off = qrow * 128 + ((c ^ (qrow & 7)) << 4);
        LDSM_X4(qf[kk][0], qf[kk][1], qf[kk][2], qf[kk][3], sb + off);
    }

    float m0 = -INFINITY, m1 = -INFINITY, l0 = 0.f, l1 = 0.f;
    float oacc[8][4];
#pragma unroll
    for (int nt = 0; nt < 8; nt++)
#pragma unroll
        for (int j = 0; j < 4; j++) oacc[nt][j] = 0.f;

    const int gq0 = qt * 64 + w * 16 + g;
    const int gq1 = gq0 + 8;
    const int krowb = (grp >> 1) * 8 + jj;
    const int vrow0 = (grp & 1) * 8 + jj;

    for (int kt = 0; kt <= ktmax; kt++) {
        CP_WAIT0();
        __syncthreads();
        if (kt < ktmax) {
            attn_load_kv(sb + 8192 + ((kt + 1) & 1) * 16384, q_g,
                         (size_t)(mbase + (kt + 1) * 64) * N3 + qcol, tid);
            CP_COMMIT();
        }

        const uint32_t stg = sb + 8192 + (kt & 1) * 16384;

        float sacc[8][4];
#pragma unroll
        for (int nt = 0; nt < 8; nt++)
#pragma unroll
            for (int j = 0; j < 4; j++) sacc[nt][j] = 0.f;

#pragma unroll
        for (int kk = 0; kk < 4; kk++) {
            uint32_t kb[8][2];
#pragma unroll
            for (int pr = 0; pr < 4; pr++) {
                int r = pr * 16 + krowb;
                int c = 2 * kk + (grp & 1);
                uint32_t off = r * 128 + ((c ^ (r & 7)) << 4);
                LDSM_X4(kb[pr*2][0], kb[pr*2][1], kb[pr*2+1][0], kb[pr*2+1][1],
                        stg + off);
            }
#pragma unroll
            for (int nt = 0; nt < 8; nt++)
                mma16816(sacc[nt], qf[kk], kb[nt]);
        }

#pragma unroll
        for (int nt = 0; nt < 8; nt++) {
            int colb = kt * 64 + nt * 8 + 2 * tig;
            sacc[nt][0] = (colb     > gq0) ? NEG_INF_F : sacc[nt][0] * 0.125f;
            sacc[nt][1] = (colb + 1 > gq0) ? NEG_INF_F : sacc[nt][1] * 0.125f;
            sacc[nt][2] = (colb     > gq1) ? NEG_INF_F : sacc[nt][2] * 0.125f;
            sacc[nt][3] = (colb + 1 > gq1) ? NEG_INF_F : sacc[nt][3] * 0.125f;
        }

        float rm0 = -INFINITY, rm1 = -INFINITY;
#pragma unroll
        for (int nt = 0; nt < 8; nt++) {
            rm0 = fmaxf(rm0, fmaxf(sacc[nt][0], sacc[nt][1]));
            rm1 = fmaxf(rm1, fmaxf(sacc[nt][2], sacc[nt][3]));
        }
        rm0 = fmaxf(rm0, __shfl_xor_sync(0xffffffffu, rm0, 1));
        rm0 = fmaxf(rm0, __shfl_xor_sync(0xffffffffu, rm0, 2));
        rm1 = fmaxf(rm1, __shfl_xor_sync(0xffffffffu, rm1, 1));
        rm1 = fmaxf(rm1, __shfl_xor_sync(0xffffffffu, rm1, 2));

        float mn0 = fmaxf(m0, rm0), mn1 = fmaxf(m1, rm1);
        float corr0 = __expf(m0 - mn0), corr1 = __expf(m1 - mn1);
        m0 = mn0; m1 = mn1;

        float rs0 = 0.f, rs1 = 0.f;
#pragma unroll
        for (int nt = 0; nt < 8; nt++) {
            sacc[nt][0] = __expf(sacc[nt][0] - mn0);
            sacc[nt][1] = __expf(sacc[nt][1] - mn0);
            sacc[nt][2] = __expf(sacc[nt][2] - mn1);
            sacc[nt][3] = __expf(sacc[nt][3] - mn1);
            rs0 += sacc[nt][0] + sacc[nt][1];
            rs1 += sacc[nt][2] + sacc[nt][3];
        }
        rs0 += __shfl_xor_sync(0xffffffffu, rs0, 1);
        rs0 += __shfl_xor_sync(0xffffffffu, rs0, 2);
        rs1 += __shfl_xor_sync(0xffffffffu, rs1, 1);
        rs1 += __shfl_xor_sync(0xffffffffu, rs1, 2);
        l0 = l0 * corr0 + rs0;
        l1 = l1 * corr1 + rs1;

#pragma unroll
        for (int nt = 0; nt < 8; nt++) {
            oacc[nt][0] *= corr0; oacc[nt][1] *= corr0;
            oacc[nt][2] *= corr1; oacc[nt][3] *= corr1;
        }

        uint32_t pa[4][4];
#pragma unroll
        for (int kk2 = 0; kk2 < 4; kk2++) {
            int a = 2 * kk2, b = a + 1;
            pa[kk2][0] = packh2(sacc[a][0], sacc[a][1]);
            pa[kk2][1] = packh2(sacc[a][2], sacc[a][3]);
            pa[kk2][2] = packh2(sacc[b][0], sacc[b][1]);
            pa[kk2][3] = packh2(sacc[b][2], sacc[b][3]);
        }

#pragma unroll
        for (int kk2 = 0; kk2 < 4; kk2++) {
            int r = kk2 * 16 + vrow0;
#pragma unroll
            for (int pr = 0; pr < 4; pr++) {
                int c = pr * 2 + (grp >> 1);
                uint32_t off = r * 128 + ((c ^ (r & 7)) << 4);
                uint32_t v0[2], v1[2];
                LDSM_X4T(v0[0], v0[1], v1[0], v1[1], stg + 8192 + off);
                mma16816(oacc[pr*2],   pa[kk2], v0);
                mma16816(oacc[pr*2+1], pa[kk2], v1);
            }
        }
    }

    const float inv0 = 1.f / l0, inv1 = 1.f / l1;
    const size_t r0 = (size_t)(mbase + qt * 64 + w * 16 + g);
    const size_t r1 = r0 + 8;
#pragma unroll
    for (int nt = 0; nt < 8; nt++) {
        int c = qcol + nt * 8 + tig * 2;
        *(__half2*)&oh[r0 * DIM + c] =
            __floats2half2_rn(oacc[nt][0] * inv0, oacc[nt][1] * inv0);
        *(__half2*)&oh[r1 * DIM + c] =
            __floats2half2_rn(oacc[nt][2] * inv1, oacc[nt][3] * inv1);
    }
}

// ---------------------------------------------------------------------------
extern "C" void kernel_launch(void* const* d_in, const int* in_sizes, int n_in,
                              void* d_out, int out_size)
{
    (void)in_sizes; (void)n_in; (void)out_size;
    const float* x     = (const float*)d_in[0];
    const float* w_qkv = (const float*)d_in[1];
    const float* b_qkv = (const float*)d_in[2];
    const float* w_o   = (const float*)d_in[3];
    const float* b_o   = (const float*)d_in[4];
    float* out = (float*)d_out;

    __half *xh, *wqt, *wot, *qkvh, *ah;
    cudaGetSymbolAddress((void**)&xh,   g_xh);
    cudaGetSymbolAddress((void**)&wqt,  g_wqkvt);
    cudaGetSymbolAddress((void**)&wot,  g_wot);
    cudaGetSymbolAddress((void**)&qkvh, g_qkvh);
    cudaGetSymbolAddress((void**)&ah,   g_ah);

    // 1) Convert x to fp16
    {
        int n4 = MROWS * DIM / 4;
        cvt_kernel<<<n4 / 256, 256>>>((const float4*)x, xh, n4);
    }
    // 2) Transpose weights to fp16
    tsplit_kernel<<<dim3(N3 / 32, DIM / 32), dim3(32, 8)>>>(w_qkv, wqt, DIM, N3);
    tsplit_kernel<<<dim3(DIM / 32, DIM / 32), dim3(32, 8)>>>(w_o, wot, DIM, DIM);

    // 3) QKV projection -> fp16 output
    gemm_hmma<1><<<dim3(N3 / 128, MROWS / 128), 256>>>(
        xh, wqt, b_qkv, nullptr, qkvh, MROWS, N3, DIM);

    // 4) Windowed causal attention (plain fp16 HMMA flash, KV-tile 64) -> fp16
    attn_hmma<<<dim3(8, 512), 128>>>(qkvh, ah);

    // 5) Output projection -> fp32 final output
    gemm_hmma<0><<<dim3(DIM / 128, MROWS / 128), 256>>>(
        ah, wot, b_o, out, nullptr, MROWS, DIM, DIM);
}